// round 1
// baseline (speedup 1.0000x reference)
#include <cuda_runtime.h>
#include <math.h>

constexpr int kB   = 16384;
constexpr int kM   = 64;
constexpr int kDV  = 64;
constexpr int kDK  = 64;
constexpr int kDQA = 128;
constexpr int kMV  = 4096;   // kM * kDV

// ---- scratch (device globals; no runtime allocation) ----
__device__ float g_content0[kB * kDQA];            // 8 MB
__device__ float g_w[kB * kM];                     // 4 MB
__device__ float g_mempre[(size_t)kB * kMV];       // 268 MB

__device__ __forceinline__ float sgm(float x) { return 1.0f / (1.0f + expf(-x)); }

__device__ __forceinline__ float f4get(const float4& v, int k) {
    return k == 0 ? v.x : k == 1 ? v.y : k == 2 ? v.z : v.w;
}

// ============================================================================
// Kernel 1: content0 = qa * sigmoid(mv_flat @ Wc0 + bc0)   (B,128)
//           write_weight = softmax(ck @ mk^T, axis=1)      (B,64)
// 128 rows / CTA, 512 threads, grid 128.
// ============================================================================
__global__ __launch_bounds__(512, 1) void k1_kernel(
    const float* __restrict__ ck, const float* __restrict__ qa,
    const float* __restrict__ mk, const float* __restrict__ mv,
    const float* __restrict__ Wc0, const float* __restrict__ bc0)
{
    extern __shared__ float sm[];
    float* As = sm;               // 128 x 68  (mv chunk / ck / logits)
    float* Bs = sm + 128 * 68;    // 64 x 132  (Wc0 chunk / mk^T)

    const int tid = threadIdx.x;
    const int tx  = tid & 15;     // 0..15
    const int ty  = tid >> 4;     // 0..31
    const int row0 = blockIdx.x * 128;

    float acc[4][8];
#pragma unroll
    for (int i = 0; i < 4; i++)
#pragma unroll
        for (int j = 0; j < 8; j++) acc[i][j] = 0.f;

    for (int k0 = 0; k0 < kMV; k0 += 64) {
        __syncthreads();
#pragma unroll
        for (int i = 0; i < 4; i++) {               // mv chunk: 128x64
            int e = tid + i * 512;
            int r = e >> 4, c4 = e & 15;
            *(float4*)&As[r * 68 + c4 * 4] =
                *(const float4*)&mv[(size_t)(row0 + r) * kMV + k0 + c4 * 4];
        }
#pragma unroll
        for (int i = 0; i < 4; i++) {               // Wc0 chunk: 64x128
            int e = tid + i * 512;
            int r = e >> 5, c4 = e & 31;
            *(float4*)&Bs[r * 132 + c4 * 4] =
                *(const float4*)&Wc0[(size_t)(k0 + r) * kDQA + c4 * 4];
        }
        __syncthreads();
#pragma unroll 2
        for (int k = 0; k < 64; k += 4) {
            float4 a4[4];
#pragma unroll
            for (int i = 0; i < 4; i++)
                a4[i] = *(float4*)&As[(ty * 4 + i) * 68 + k];
#pragma unroll
            for (int kk = 0; kk < 4; kk++) {
                float4 b0 = *(float4*)&Bs[(k + kk) * 132 + tx * 8];
                float4 b1 = *(float4*)&Bs[(k + kk) * 132 + tx * 8 + 4];
#pragma unroll
                for (int i = 0; i < 4; i++) {
                    float a = f4get(a4[i], kk);
                    acc[i][0] += a * b0.x; acc[i][1] += a * b0.y;
                    acc[i][2] += a * b0.z; acc[i][3] += a * b0.w;
                    acc[i][4] += a * b1.x; acc[i][5] += a * b1.y;
                    acc[i][6] += a * b1.z; acc[i][7] += a * b1.w;
                }
            }
        }
    }
    // content0 = qa * sigmoid(acc + bc0)
#pragma unroll
    for (int i = 0; i < 4; i++) {
        int r = row0 + ty * 4 + i;
#pragma unroll
        for (int j = 0; j < 8; j++) {
            int c = tx * 8 + j;
            g_content0[r * kDQA + c] = qa[r * kDQA + c] * sgm(acc[i][j] + bc0[c]);
        }
    }

    // ---- write weight: logits = ck @ mk^T, softmax over m ----
    __syncthreads();
#pragma unroll
    for (int i = 0; i < 4; i++) {                   // ck tile 128x64 -> As
        int e = tid + i * 512;
        int r = e >> 4, c4 = e & 15;
        *(float4*)&As[r * 68 + c4 * 4] =
            *(const float4*)&ck[(size_t)(row0 + r) * kDK + c4 * 4];
    }
#pragma unroll
    for (int i = 0; i < 8; i++) {                   // mk transposed -> Bs[k][m]
        int e = tid + i * 512;
        int m_ = e >> 6, kk = e & 63;
        Bs[kk * 68 + m_] = mk[m_ * kDK + kk];
    }
    __syncthreads();
    float lg[4][4];
#pragma unroll
    for (int i = 0; i < 4; i++)
#pragma unroll
        for (int j = 0; j < 4; j++) lg[i][j] = 0.f;
#pragma unroll 4
    for (int k = 0; k < 64; k++) {
        float a[4];
#pragma unroll
        for (int i = 0; i < 4; i++) a[i] = As[(ty * 4 + i) * 68 + k];
        float4 b = *(float4*)&Bs[k * 68 + tx * 4];
#pragma unroll
        for (int i = 0; i < 4; i++) {
            lg[i][0] += a[i] * b.x; lg[i][1] += a[i] * b.y;
            lg[i][2] += a[i] * b.z; lg[i][3] += a[i] * b.w;
        }
    }
    __syncthreads();
#pragma unroll
    for (int i = 0; i < 4; i++)
#pragma unroll
        for (int j = 0; j < 4; j++)
            As[(ty * 4 + i) * 68 + tx * 4 + j] = lg[i][j];
    __syncthreads();
    if (tid < 128) {
        int r = tid;
        float mx = -1e30f;
        for (int m_ = 0; m_ < kM; m_++) mx = fmaxf(mx, As[r * 68 + m_]);
        float s = 0.f;
        for (int m_ = 0; m_ < kM; m_++) {
            float e = expf(As[r * 68 + m_] - mx);
            As[r * 68 + m_] = e; s += e;
        }
        float inv = 1.f / s;
        for (int m_ = 0; m_ < kM; m_++)
            g_w[(row0 + r) * kM + m_] = As[r * 68 + m_] * inv;
    }
}

// ============================================================================
// Kernel 2: everything else, fused per 128-row tile.
//   gate1 chunk = sigmoid(c0 @ Wm1[:,chunk] + bm1)  -> memory_pre chunk
//   accumulate memory_pre @ {Wemv, Wzmv, Wamv}
//   erase/zt/add signals, then final elementwise combine.
// ============================================================================
__global__ __launch_bounds__(512, 1) void k2_kernel(
    const float* __restrict__ mv,
    const float* __restrict__ We,   const float* __restrict__ be,
    const float* __restrict__ Wemv, const float* __restrict__ bemv,
    const float* __restrict__ Wza,  const float* __restrict__ bza,
    const float* __restrict__ Wamv, const float* __restrict__ bamv,
    const float* __restrict__ Wm1,  const float* __restrict__ bm1,
    const float* __restrict__ Wz,   const float* __restrict__ bz,
    const float* __restrict__ Wzmv, const float* __restrict__ bzmv,
    float* __restrict__ out)
{
    extern __shared__ float sm[];
    float* c0s  = sm;                   // 128 x 132 : content0 tile
    float* bufA = c0s + 128 * 132;      // 128 x 68  : Wm1 chunk / We / Wz / add
    float* buf3 = bufA + 128 * 68;      // 3 x 64 x 68: W*mv chunks / erase+Wza
    float* bufM = buf3 + 3 * 64 * 68;   // 128 x 68  : memory_pre chunk / zt

    const int tid = threadIdx.x;
    const int tx  = tid & 15;
    const int ty  = tid >> 4;
    const int row0 = blockIdx.x * 128;
    const int col  = tx * 4;

#pragma unroll
    for (int i = 0; i < 8; i++) {                   // content0 tile 128x128
        int e = tid + i * 512;
        int r = e >> 5, c4 = e & 31;
        *(float4*)&c0s[r * 132 + c4 * 4] =
            *(const float4*)&g_content0[(size_t)(row0 + r) * kDQA + c4 * 4];
    }

    float acce[4][4], accz[4][4], acca[4][4];
#pragma unroll
    for (int i = 0; i < 4; i++)
#pragma unroll
        for (int j = 0; j < 4; j++) { acce[i][j] = 0.f; accz[i][j] = 0.f; acca[i][j] = 0.f; }

    for (int mch = 0; mch < kM; mch++) {
#pragma unroll
        for (int i = 0; i < 4; i++) {               // Wm1[:, chunk] 128x64
            int e = tid + i * 512;
            int r = e >> 4, c4 = e & 15;
            *(float4*)&bufA[r * 68 + c4 * 4] =
                *(const float4*)&Wm1[(size_t)r * kMV + mch * 64 + c4 * 4];
        }
#pragma unroll
        for (int i = 0; i < 2; i++) {               // W*mv[chunk,:] 64x64 each
            int e = tid + i * 512;
            int r = e >> 4, c4 = e & 15;
            size_t g = (size_t)(mch * 64 + r) * kDV + c4 * 4;
            *(float4*)&buf3[             r * 68 + c4 * 4] = *(const float4*)&Wemv[g];
            *(float4*)&buf3[64 * 68   +  r * 68 + c4 * 4] = *(const float4*)&Wzmv[g];
            *(float4*)&buf3[2 * 64 * 68 + r * 68 + c4 * 4] = *(const float4*)&Wamv[g];
        }
        __syncthreads();

        // g1pre = c0 @ Wm1chunk  (128x64, K=128)
        float a1[4][4];
#pragma unroll
        for (int i = 0; i < 4; i++)
#pragma unroll
            for (int j = 0; j < 4; j++) a1[i][j] = 0.f;
#pragma unroll 2
        for (int k = 0; k < kDQA; k += 4) {
            float4 a4[4];
#pragma unroll
            for (int i = 0; i < 4; i++)
                a4[i] = *(float4*)&c0s[(ty * 4 + i) * 132 + k];
#pragma unroll
            for (int kk = 0; kk < 4; kk++) {
                float4 b = *(float4*)&bufA[(k + kk) * 68 + col];
#pragma unroll
                for (int i = 0; i < 4; i++) {
                    float a = f4get(a4[i], kk);
                    a1[i][0] += a * b.x; a1[i][1] += a * b.y;
                    a1[i][2] += a * b.z; a1[i][3] += a * b.w;
                }
            }
        }
        float bm[4];
#pragma unroll
        for (int j = 0; j < 4; j++) bm[j] = bm1[mch * 64 + col + j];
#pragma unroll
        for (int i = 0; i < 4; i++) {
            int r = row0 + ty * 4 + i;
            float4 m4 = *(const float4*)&mv[(size_t)r * kMV + mch * 64 + col];
            float4 mp;
            mp.x = m4.x * sgm(a1[i][0] + bm[0]);
            mp.y = m4.y * sgm(a1[i][1] + bm[1]);
            mp.z = m4.z * sgm(a1[i][2] + bm[2]);
            mp.w = m4.w * sgm(a1[i][3] + bm[3]);
            *(float4*)&bufM[(ty * 4 + i) * 68 + col] = mp;
            *(float4*)&g_mempre[(size_t)r * kMV + mch * 64 + col] = mp;
        }
        __syncthreads();

        // accumulate the three K=4096 reductions
#pragma unroll 2
        for (int k = 0; k < 64; k += 4) {
            float4 a4[4];
#pragma unroll
            for (int i = 0; i < 4; i++)
                a4[i] = *(float4*)&bufM[(ty * 4 + i) * 68 + k];
#pragma unroll
            for (int kk = 0; kk < 4; kk++) {
                float4 eb = *(float4*)&buf3[             (k + kk) * 68 + col];
                float4 zb = *(float4*)&buf3[64 * 68   +  (k + kk) * 68 + col];
                float4 ab = *(float4*)&buf3[2 * 64 * 68 + (k + kk) * 68 + col];
#pragma unroll
                for (int i = 0; i < 4; i++) {
                    float a = f4get(a4[i], kk);
                    acce[i][0] += a * eb.x; acce[i][1] += a * eb.y;
                    acce[i][2] += a * eb.z; acce[i][3] += a * eb.w;
                    accz[i][0] += a * zb.x; accz[i][1] += a * zb.y;
                    accz[i][2] += a * zb.z; accz[i][3] += a * zb.w;
                    acca[i][0] += a * ab.x; acca[i][1] += a * ab.y;
                    acca[i][2] += a * ab.z; acca[i][3] += a * ab.w;
                }
            }
        }
        __syncthreads();
    }

    // ---- e1pre = c0 @ We ----
#pragma unroll
    for (int i = 0; i < 4; i++) {
        int e = tid + i * 512;
        int r = e >> 4, c4 = e & 15;
        *(float4*)&bufA[r * 68 + c4 * 4] = *(const float4*)&We[(size_t)r * kDV + c4 * 4];
    }
    __syncthreads();
    float e1p[4][4];
#pragma unroll
    for (int i = 0; i < 4; i++)
#pragma unroll
        for (int j = 0; j < 4; j++) e1p[i][j] = 0.f;
#pragma unroll 2
    for (int k = 0; k < kDQA; k += 4) {
        float4 a4[4];
#pragma unroll
        for (int i = 0; i < 4; i++) a4[i] = *(float4*)&c0s[(ty * 4 + i) * 132 + k];
#pragma unroll
        for (int kk = 0; kk < 4; kk++) {
            float4 b = *(float4*)&bufA[(k + kk) * 68 + col];
#pragma unroll
            for (int i = 0; i < 4; i++) {
                float a = f4get(a4[i], kk);
                e1p[i][0] += a * b.x; e1p[i][1] += a * b.y;
                e1p[i][2] += a * b.z; e1p[i][3] += a * b.w;
            }
        }
    }
    __syncthreads();
    // ---- zcpre = c0 @ Wz ----
#pragma unroll
    for (int i = 0; i < 4; i++) {
        int e = tid + i * 512;
        int r = e >> 4, c4 = e & 15;
        *(float4*)&bufA[r * 68 + c4 * 4] = *(const float4*)&Wz[(size_t)r * kDV + c4 * 4];
    }
    __syncthreads();
    float zcp[4][4];
#pragma unroll
    for (int i = 0; i < 4; i++)
#pragma unroll
        for (int j = 0; j < 4; j++) zcp[i][j] = 0.f;
#pragma unroll 2
    for (int k = 0; k < kDQA; k += 4) {
        float4 a4[4];
#pragma unroll
        for (int i = 0; i < 4; i++) a4[i] = *(float4*)&c0s[(ty * 4 + i) * 132 + k];
#pragma unroll
        for (int kk = 0; kk < 4; kk++) {
            float4 b = *(float4*)&bufA[(k + kk) * 68 + col];
#pragma unroll
            for (int i = 0; i < 4; i++) {
                float a = f4get(a4[i], kk);
                zcp[i][0] += a * b.x; zcp[i][1] += a * b.y;
                zcp[i][2] += a * b.z; zcp[i][3] += a * b.w;
            }
        }
    }

    // erase -> buf3[0:8704], zt -> bufM
    float bev[4], bemvv[4], bzv[4], bzmvv[4];
#pragma unroll
    for (int j = 0; j < 4; j++) {
        bev[j] = be[col + j]; bemvv[j] = bemv[col + j];
        bzv[j] = bz[col + j]; bzmvv[j] = bzmv[col + j];
    }
#pragma unroll
    for (int i = 0; i < 4; i++) {
        int lr = ty * 4 + i;
#pragma unroll
        for (int j = 0; j < 4; j++) {
            float er = sgm(sgm(e1p[i][j] + bev[j]) + sgm(acce[i][j] + bemvv[j]));
            buf3[lr * 68 + col + j] = er;
            float zt = sgm(zcp[i][j] + bzv[j] + accz[i][j] + bzmvv[j]);
            bufM[lr * 68 + col + j] = zt;
        }
    }
    __syncthreads();
    // stage Wza at buf3 + 8704
#pragma unroll
    for (int i = 0; i < 2; i++) {
        int e = tid + i * 512;
        int r = e >> 4, c4 = e & 15;
        *(float4*)&buf3[8704 + r * 68 + c4 * 4] =
            *(const float4*)&Wza[(size_t)r * kDV + c4 * 4];
    }
    __syncthreads();
    // tapre = zt @ Wza  (K=64)
    float tap[4][4];
#pragma unroll
    for (int i = 0; i < 4; i++)
#pragma unroll
        for (int j = 0; j < 4; j++) tap[i][j] = 0.f;
#pragma unroll 2
    for (int k = 0; k < 64; k += 4) {
        float4 a4[4];
#pragma unroll
        for (int i = 0; i < 4; i++) a4[i] = *(float4*)&bufM[(ty * 4 + i) * 68 + k];
#pragma unroll
        for (int kk = 0; kk < 4; kk++) {
            float4 b = *(float4*)&buf3[8704 + (k + kk) * 68 + col];
#pragma unroll
            for (int i = 0; i < 4; i++) {
                float a = f4get(a4[i], kk);
                tap[i][0] += a * b.x; tap[i][1] += a * b.y;
                tap[i][2] += a * b.z; tap[i][3] += a * b.w;
            }
        }
    }
    float bzav[4], bamvv[4];
#pragma unroll
    for (int j = 0; j < 4; j++) { bzav[j] = bza[col + j]; bamvv[j] = bamv[col + j]; }
#pragma unroll
    for (int i = 0; i < 4; i++) {
        int lr = ty * 4 + i;
#pragma unroll
        for (int j = 0; j < 4; j++) {
            float ad = tanhf(tanhf(tap[i][j] + bzav[j]) + tanhf(acca[i][j] + bamvv[j]));
            bufA[lr * 68 + col + j] = ad;   // add signal
        }
    }
    __syncthreads();

    // ---- final combine: out = mempre*(1 - w*erase) + w*add ----
    float4 e4[4], a4f[4];
#pragma unroll
    for (int i = 0; i < 4; i++) {
        e4[i]  = *(float4*)&buf3[(ty * 4 + i) * 68 + col];
        a4f[i] = *(float4*)&bufA[(ty * 4 + i) * 68 + col];
    }
    for (int mm = 0; mm < kM; mm++) {
#pragma unroll
        for (int i = 0; i < 4; i++) {
            int r = row0 + ty * 4 + i;
            float w = g_w[r * kM + mm];
            float4 mp = *(float4*)&g_mempre[(size_t)r * kMV + mm * 64 + col];
            float4 o;
            o.x = mp.x * (1.f - w * e4[i].x) + w * a4f[i].x;
            o.y = mp.y * (1.f - w * e4[i].y) + w * a4f[i].y;
            o.z = mp.z * (1.f - w * e4[i].z) + w * a4f[i].z;
            o.w = mp.w * (1.f - w * e4[i].w) + w * a4f[i].w;
            *(float4*)&out[(size_t)r * kMV + mm * 64 + col] = o;
        }
    }
}

extern "C" void kernel_launch(void* const* d_in, const int* in_sizes, int n_in,
                              void* d_out, int out_size)
{
    const float* ck   = (const float*)d_in[0];
    const float* qa   = (const float*)d_in[1];
    const float* mk   = (const float*)d_in[2];
    const float* mv   = (const float*)d_in[3];
    const float* We   = (const float*)d_in[4];
    const float* be   = (const float*)d_in[5];
    const float* Wemv = (const float*)d_in[6];
    const float* bemv = (const float*)d_in[7];
    const float* Wza  = (const float*)d_in[8];
    const float* bza  = (const float*)d_in[9];
    const float* Wamv = (const float*)d_in[10];
    const float* bamv = (const float*)d_in[11];
    const float* Wc0  = (const float*)d_in[12];
    const float* bc0  = (const float*)d_in[13];
    const float* Wm1  = (const float*)d_in[14];
    const float* bm1  = (const float*)d_in[15];
    const float* Wz   = (const float*)d_in[16];
    const float* bz   = (const float*)d_in[17];
    const float* Wzmv = (const float*)d_in[18];
    const float* bzmv = (const float*)d_in[19];

    const int smem1 = (128 * 68 + 64 * 132) * 4;                       // 68608
    const int smem2 = (128 * 132 + 128 * 68 + 3 * 64 * 68 + 128 * 68) * 4; // 189440
    cudaFuncSetAttribute(k1_kernel, cudaFuncAttributeMaxDynamicSharedMemorySize, smem1);
    cudaFuncSetAttribute(k2_kernel, cudaFuncAttributeMaxDynamicSharedMemorySize, smem2);

    k1_kernel<<<kB / 128, 512, smem1>>>(ck, qa, mk, mv, Wc0, bc0);
    k2_kernel<<<kB / 128, 512, smem2>>>(mv, We, be, Wemv, bemv, Wza, bza,
                                        Wamv, bamv, Wm1, bm1, Wz, bz,
                                        Wzmv, bzmv, (float*)d_out);
}